// round 4
// baseline (speedup 1.0000x reference)
#include <cuda_runtime.h>
#include <float.h>

// Fused MaxPool(2x2,s1,SAME) -> depthwise 3x3 binomial blur -> AvgPool(2x2,s2)
// == separable 4x4 stencil w=(1,3,3,1)/8 stride 2 over maxpool output y.
//
// R4: cp.async (LDGSTS) staging into a per-warp 4-slot smem column ring,
// prefetch distance 3 -> 21 loads in flight per warp with ~75 live regs,
// 5 CTAs/SM. No __syncthreads: each warp owns its ring slots; per-thread
// cp.async group semantics order producer vs consumer.

#define NROWP  28
#define ROWSTR (112*64)     // float2 per x row
#define PXSTR  64           // float2 per pixel

__device__ __forceinline__ float2 f2max(float2 a, float2 b) {
    return make_float2(fmaxf(a.x,b.x), fmaxf(a.y,b.y));
}
__device__ __forceinline__ void f2fma(float2& a, float w, float2 v) {
    a.x = fmaf(w, v.x, a.x); a.y = fmaf(w, v.y, a.y);
}

// Issue one column (7 rows x 8B/thread) into ring slot (T)&3.
// Addresses are pre-clamped; garbage values only ever reach lanes that the
// compute side zeroes/skips (see boundary analysis in comments below).
#define ISSUE(T) do {                                                        \
    const int  _c  = xc0 + (T);                                              \
    const int  _cc = _c < 0 ? 0 : (_c > 111 ? 111 : _c);                     \
    const float2* _gp = gbase + (long long)_cc * PXSTR;                      \
    const unsigned _sa = swBase + (((T) & 3) * 7) * 256;                     \
    _Pragma("unroll")                                                        \
    for (int _k = 0; _k < 7; _k++) {                                         \
        asm volatile("cp.async.ca.shared.global [%0], [%1], 8;\n"            \
                     :: "r"(_sa + _k * 256), "l"(_gp + rowOff[_k])           \
                     : "memory");                                            \
    }                                                                        \
    asm volatile("cp.async.commit_group;\n" ::: "memory");                   \
} while (0)

__global__ void __launch_bounds__(128, 5)
mbp_kernel(const float2* __restrict__ x, float2* __restrict__ out) {
    // [warp][slot][row][lane] : 4*4*7*32*8 = 28672 B
    __shared__ float2 sbuf[4][4][7][32];

    const int lane = threadIdx.x;
    const int wy   = threadIdx.y;
    const int wid  = blockIdx.x * 4 + wy;      // 7168 warp tasks
    const int chHalf = wid & 1;
    const int strip  = wid >> 1;               // 3584 strips
    const int cj = strip & 3;                  // 4 col chunks of 14
    const int s2 = strip >> 2;
    const int ti = s2 % NROWP;                 // 28 row pairs
    const int b  = s2 / NROWP;

    const int oi0 = 2 * ti;
    const int oj0 = 14 * cj;
    const int xr0 = 4 * ti - 1;
    const int xc0 = 28 * cj - 1;

    const float2 NEG  = make_float2(-FLT_MAX, -FLT_MAX);
    const float2 ZERO = make_float2(0.f, 0.f);
    const float wv0 = 0.125f, wv1 = 0.375f;    // (1,3,3,1)/8

    // Boundary analysis:
    //  row 0 OOB (top strip)    -> only feeds yc[0], which is zeroed   -> clamp
    //  row 6 OOB (bottom strip) -> only feeds yc[5], which is zeroed   -> clamp
    //  row 5 OOB (bottom strip) -> feeds cm[4] too -> must be NEG      -> select
    //  col -1  (left chunk)     -> only feeds skipped y col -1         -> clamp
    //  col 112 (right, t=29)    -> feeds valid y col 111 -> cm := NEG  -> select
    //  col 113 (right, t=30)    -> only feeds skipped y col 112        -> clamp
    const bool okTop     = (ti != 0);
    const bool okBot     = (ti != NROWP - 1);
    const bool leftSkip  = (cj == 0);
    const bool rightSkip = (cj == 3);

    int rowOff[7];                             // clamped, in float2 units
#pragma unroll
    for (int k = 0; k < 7; k++) {
        int gr = xr0 + k;
        gr = gr < 0 ? 0 : (gr > 111 ? 111 : gr);
        rowOff[k] = gr * ROWSTR;
    }
    const float2* gbase = x + (size_t)b * 112 * 112 * 64 + chHalf * 32 + lane;

    const unsigned swBase =
        (unsigned)__cvta_generic_to_shared(&sbuf[wy][0][0][lane]);

    float2* ob = out + ((size_t)(b * 56 + oi0) * 56 + oj0) * 64
                     + chHalf * 32 + lane;

    // Prologue: fill 3 ring slots.
    ISSUE(0); ISSUE(1); ISSUE(2);

    float2 cmPrev[6];
    float2 acc[2][2];
    acc[0][0]=ZERO; acc[0][1]=ZERO; acc[1][0]=ZERO; acc[1][1]=ZERO;

#pragma unroll
    for (int t = 0; t <= 30; t++) {
        // Wait until column t's group has landed.
        if (t <= 28)      asm volatile("cp.async.wait_group 2;\n" ::: "memory");
        else if (t == 29) asm volatile("cp.async.wait_group 1;\n" ::: "memory");
        else              asm volatile("cp.async.wait_group 0;\n" ::: "memory");

        const int slot = t & 3;
        float2 xv[7];
#pragma unroll
        for (int k = 0; k < 7; k++) xv[k] = sbuf[wy][slot][k][lane];
        if (!okBot) xv[5] = NEG;

        // Prefetch column t+3 (overwrites slot consumed at iter t-1; its
        // global->smem write lands hundreds of cycles after this issue).
        if (t + 3 <= 30) ISSUE(t + 3);

        float2 cm[6];
#pragma unroll
        for (int k = 0; k < 6; k++) cm[k] = f2max(xv[k], xv[k+1]);
        if (t == 29 && rightSkip) {
#pragma unroll
            for (int k = 0; k < 6; k++) cm[k] = NEG;   // x col 112 pad = -inf
        }

        if (t >= 1) {
            const int ty = t - 1;                       // y col 0..29
            const bool skip = (ty == 0 && leftSkip) || (ty == 29 && rightSkip);
            if (!skip) {
                float2 yc[6];
#pragma unroll
                for (int k = 0; k < 6; k++) yc[k] = f2max(cmPrev[k], cm[k]);
                if (!okTop) yc[0] = ZERO;               // blur zero pad
                if (!okBot) yc[5] = ZERO;

                const int   m  = ty >> 1;
                const float wA = (ty & 1) ? wv1 : wv0;
                const float wB = (ty & 1) ? wv0 : wv1;
#pragma unroll
                for (int rl = 0; rl < 2; rl++) {
                    float2 V = ZERO;
                    f2fma(V, wv0, yc[2*rl + 0]);
                    f2fma(V, wv1, yc[2*rl + 1]);
                    f2fma(V, wv1, yc[2*rl + 2]);
                    f2fma(V, wv0, yc[2*rl + 3]);
                    if (m < 14) f2fma(acc[rl][m & 1], wA, V);
                    if (m >= 1) f2fma(acc[rl][(m & 1) ^ 1], wB, V);
                }
            }
            if ((ty & 1) && ty >= 3) {                  // out col wl complete
                const int wl = (ty >> 1) - 1, s = wl & 1;
#pragma unroll
                for (int rl = 0; rl < 2; rl++) {
                    ob[((size_t)rl * 56 + wl) * 64] = acc[rl][s];
                    acc[rl][s] = ZERO;
                }
            }
        }
#pragma unroll
        for (int k = 0; k < 6; k++) cmPrev[k] = cm[k];
    }
}

extern "C" void kernel_launch(void* const* d_in, const int* in_sizes, int n_in,
                              void* d_out, int out_size) {
    const float2* x = (const float2*)d_in[0];   // (32,112,112,128) f32
    // d_in[1] = blur kernel, baked into (1,3,3,1)/8
    float2* out = (float2*)d_out;               // (32,56,56,128) f32

    // 3584 strips x 2 channel halves = 7168 warp tasks, 4 warps/CTA
    dim3 block(32, 4);
    dim3 grid(7168 / 4);                        // 1792 blocks
    mbp_kernel<<<grid, block>>>(x, out);
}

// round 5
// speedup vs baseline: 1.1445x; 1.1445x over previous
#include <cuda_runtime.h>
#include <float.h>

// Fused MaxPool(2x2,s1,SAME) -> depthwise 3x3 binomial blur -> AvgPool(2x2,s2)
// == separable 4x4 stencil w=(1,3,3,1)/8 stride 2 over maxpool output y.
//
// R5: direct-LDG register pipelining (R3 family), per-column ring of 3
// buffers with prefetch distance 2 (14 loads in flight/warp), clamped-pointer
// boundary handling, <=96 regs -> 5 CTAs/SM.

#define NROWP  28
#define ROWSTR (112*64)     // float2 per x row
#define PXSTR  64           // float2 per pixel

__device__ __forceinline__ float2 f2max(float2 a, float2 b) {
    return make_float2(fmaxf(a.x,b.x), fmaxf(a.y,b.y));
}
__device__ __forceinline__ void f2fma(float2& a, float w, float2 v) {
    a.x = fmaf(w, v.x, a.x); a.y = fmaf(w, v.y, a.y);
}

// Load x column (7 rows) into ring slot (T)%3, then advance the column
// pointers unless frozen at the left (T==0, cj==0 column is pre-clamped) or
// right (T>=28, cj==3, cols 112/113 clamp to 111) edge. All addresses are
// in-bounds by construction; out-of-range VALUES are neutralized at consume
// time (row5 NEG select, t==29 cm:=NEG, yc[0]/yc[5] zeroing).
#define ISSUE(T) do {                                                     \
    const int _s = (T) % 3;                                               \
    xbuf[_s][0] = __ldg(topp);                                            \
    xbuf[_s][1] = __ldg(colp + 0*ROWSTR);                                 \
    xbuf[_s][2] = __ldg(colp + 1*ROWSTR);                                 \
    xbuf[_s][3] = __ldg(colp + 2*ROWSTR);                                 \
    xbuf[_s][4] = __ldg(colp + 3*ROWSTR);                                 \
    xbuf[_s][5] = __ldg(b5p);                                             \
    xbuf[_s][6] = __ldg(b6p);                                             \
    if (!(leftSkip && (T) == 0) && !(rightSkip && (T) >= 28)) {           \
        topp += PXSTR; colp += PXSTR; b5p += PXSTR; b6p += PXSTR;         \
    }                                                                     \
} while (0)

__global__ void __launch_bounds__(128, 5)
mbp_kernel(const float2* __restrict__ x, float2* __restrict__ out) {
    const int lane   = threadIdx.x;
    const int wid    = blockIdx.x * 4 + threadIdx.y;   // 7168 warp tasks
    const int chHalf = wid & 1;
    const int strip  = wid >> 1;                       // 3584 strips
    const int cj = strip & 3;                          // 4 col chunks of 14
    const int s2 = strip >> 2;
    const int ti = s2 % NROWP;                         // 28 row pairs
    const int b  = s2 / NROWP;

    const int oi0 = 2 * ti;
    const int oj0 = 14 * cj;
    const int xr0 = 4 * ti - 1;                        // first x row
    const int xc0 = 28 * cj - 1;                       // first x col

    const bool okTop     = (ti != 0);
    const bool okBot     = (ti != NROWP - 1);
    const bool leftSkip  = (cj == 0);
    const bool rightSkip = (cj == 3);

    const float2 NEG  = make_float2(-FLT_MAX, -FLT_MAX);
    const float2 ZERO = make_float2(0.f, 0.f);
    const float wv0 = 0.125f, wv1 = 0.375f;            // (1,3,3,1)/8

    const float2* gbase = x + (size_t)b * 112 * 112 * 64 + chHalf * 32 + lane;
    const int c0 = (xc0 < 0) ? 0 : xc0;                // left clamp
    // Row pointers (row clamped so every address is in-bounds):
    //  topp: row xr0   (top strip: -1 -> 0; feeds yc[0] which is zeroed)
    //  colp: row xr0+1 (rows xr0+1..xr0+4 always valid)
    //  b5p : row xr0+5 (bottom strip: 112 -> 111; value replaced by NEG)
    //  b6p : row xr0+6 (bottom strip: 113 -> 111; feeds yc[5], zeroed)
    const float2* topp = gbase + (size_t)(okTop ? xr0 : 0)       * ROWSTR + (size_t)c0 * PXSTR;
    const float2* colp = gbase + (size_t)(xr0 + 1)               * ROWSTR + (size_t)c0 * PXSTR;
    const float2* b5p  = gbase + (size_t)(okBot ? xr0 + 5 : 111) * ROWSTR + (size_t)c0 * PXSTR;
    const float2* b6p  = gbase + (size_t)(okBot ? xr0 + 6 : 111) * ROWSTR + (size_t)c0 * PXSTR;

    float2* ob = out + ((size_t)(b * 56 + oi0) * 56 + oj0) * 64
                     + chHalf * 32 + lane;

    float2 xbuf[3][7];
    float2 cmPrev[6];
    float2 acc[2][2];
    acc[0][0]=ZERO; acc[0][1]=ZERO; acc[1][0]=ZERO; acc[1][1]=ZERO;

    // Prologue: two columns in flight.
    ISSUE(0); ISSUE(1);

#pragma unroll
    for (int t = 0; t <= 30; t++) {
        if (t + 2 <= 30) ISSUE(t + 2);                 // keep 14 loads in flight

        const int slot = t % 3;
        float2 xv5 = okBot ? xbuf[slot][5] : NEG;      // x row 112 pad = -inf

        float2 cm[6];                                  // y col = max over row pairs
        cm[0] = f2max(xbuf[slot][0], xbuf[slot][1]);
        cm[1] = f2max(xbuf[slot][1], xbuf[slot][2]);
        cm[2] = f2max(xbuf[slot][2], xbuf[slot][3]);
        cm[3] = f2max(xbuf[slot][3], xbuf[slot][4]);
        cm[4] = f2max(xbuf[slot][4], xv5);
        cm[5] = f2max(xv5,           xbuf[slot][6]);

        if (t == 29 && rightSkip) {                    // x col 112 pad = -inf
#pragma unroll
            for (int k = 0; k < 6; k++) cm[k] = NEG;
        }

        if (t >= 1) {
            const int ty = t - 1;                      // y col index 0..29
            const bool skip = (ty == 0 && leftSkip) || (ty == 29 && rightSkip);
            if (!skip) {
                float2 yc[6];
#pragma unroll
                for (int k = 0; k < 6; k++) yc[k] = f2max(cmPrev[k], cm[k]);
                if (!okTop) yc[0] = ZERO;              // blur zero pad rows
                if (!okBot) yc[5] = ZERO;

                const int   m  = ty >> 1;              // literal after unroll
                const float wA = (ty & 1) ? wv1 : wv0;
                const float wB = (ty & 1) ? wv0 : wv1;
#pragma unroll
                for (int rl = 0; rl < 2; rl++) {
                    float2 V = ZERO;                   // vertical (1,3,3,1)/8
                    f2fma(V, wv0, yc[2*rl + 0]);
                    f2fma(V, wv1, yc[2*rl + 1]);
                    f2fma(V, wv1, yc[2*rl + 2]);
                    f2fma(V, wv0, yc[2*rl + 3]);
                    if (m < 14) f2fma(acc[rl][m & 1], wA, V);
                    if (m >= 1) f2fma(acc[rl][(m & 1) ^ 1], wB, V);
                }
            }
            if ((ty & 1) && ty >= 3) {                 // out col wl complete
                const int wl = (ty >> 1) - 1, s = wl & 1;
#pragma unroll
                for (int rl = 0; rl < 2; rl++) {
                    ob[((size_t)rl * 56 + wl) * 64] = acc[rl][s];
                    acc[rl][s] = ZERO;
                }
            }
        }
#pragma unroll
        for (int k = 0; k < 6; k++) cmPrev[k] = cm[k]; // renamed away by unroll
    }
}

extern "C" void kernel_launch(void* const* d_in, const int* in_sizes, int n_in,
                              void* d_out, int out_size) {
    const float2* x = (const float2*)d_in[0];   // (32,112,112,128) f32
    // d_in[1] = blur kernel, baked into (1,3,3,1)/8
    float2* out = (float2*)d_out;               // (32,56,56,128) f32

    // 3584 strips x 2 channel halves = 7168 warp tasks, 4 warps/CTA
    dim3 block(32, 4);
    dim3 grid(7168 / 4);                        // 1792 blocks
    mbp_kernel<<<grid, block>>>(x, out);
}